// round 13
// baseline (speedup 1.0000x reference)
#include <cuda_runtime.h>
#include <cuda_fp16.h>
#include <math.h>
#include <stdint.h>

#define B_   4
#define S_   2048
#define D_   1024
#define H_   16
#define DK_  64
#define F_   4096
#define NTOK (B_ * S_)
#define LD3  (3 * D_)

// ---------------- scratch (device globals: no allocation allowed) ----------
__device__ __half g_h[(size_t)NTOK * D_];
__device__ __half g_qkv[(size_t)NTOK * LD3];   // q | k | v interleaved per row
__device__ __half g_ctx[(size_t)NTOK * D_];
__device__ __half g_a[(size_t)NTOK * F_];
__device__ float  g_vmean[B_ * D_];
__device__ float  g_bqkv[LD3];
// transposed fp16 weights [N, K], single plane
__device__ __half g_wqkvt[(size_t)LD3 * D_];   // Wq^T | Wk^T | Wv^T stacked
__device__ __half g_wot[(size_t)D_ * D_];
__device__ __half g_w1t[(size_t)F_ * D_];
__device__ __half g_w2t[(size_t)D_ * F_];

// ======================= helpers ============================================
__device__ __forceinline__ uint32_t smem_u32(const void* p) {
    uint32_t a;
    asm("{ .reg .u64 t; cvta.to.shared.u64 t, %1; cvt.u32.u64 %0, t; }"
        : "=r"(a) : "l"(p));
    return a;
}

__device__ __forceinline__ void ldsm_x4(uint32_t* r, uint32_t addr) {
    asm volatile("ldmatrix.sync.aligned.m8n8.x4.shared.b16 {%0,%1,%2,%3}, [%4];"
        : "=r"(r[0]), "=r"(r[1]), "=r"(r[2]), "=r"(r[3]) : "r"(addr));
}

__device__ __forceinline__ void mma_f16(float* c, const uint32_t* a,
                                        uint32_t b0, uint32_t b1) {
    asm volatile(
        "mma.sync.aligned.m16n8k16.row.col.f32.f16.f16.f32 "
        "{%0,%1,%2,%3}, {%4,%5,%6,%7}, {%8,%9}, {%0,%1,%2,%3};"
        : "+f"(c[0]), "+f"(c[1]), "+f"(c[2]), "+f"(c[3])
        : "r"(a[0]), "r"(a[1]), "r"(a[2]), "r"(a[3]), "r"(b0), "r"(b1));
}

__device__ __forceinline__ void cp16(uint32_t dst, const void* src) {
    asm volatile("cp.async.cg.shared.global [%0], [%1], 16;" :: "r"(dst), "l"(src));
}
#define CP_COMMIT() asm volatile("cp.async.commit_group;" ::: "memory")
#define CP_WAIT3()  asm volatile("cp.async.wait_group 3;" ::: "memory")

__device__ __forceinline__ uint2 cvt_f16(float4 v) {
    __half2 h01 = __floats2half2_rn(v.x, v.y);
    __half2 h23 = __floats2half2_rn(v.z, v.w);
    return make_uint2(*(uint32_t*)&h01, *(uint32_t*)&h23);
}
__device__ __forceinline__ uint32_t pack2_f16(float a, float b) {
    __half2 h = __floats2half2_rn(a, b);
    return *(uint32_t*)&h;
}

__device__ __forceinline__ float gelu_exact(float x) {
    return 0.5f * x * (1.0f + erff(x * 0.70710678118654752f));
}

// ======================= weight transpose + fp16 cvt ========================
__global__ __launch_bounds__(256) void transpose_cvt_kernel(
    const float* __restrict__ W, __half* __restrict__ Wt, int R, int C)
{
    __shared__ float t[32][33];
    int c0 = blockIdx.x * 32, r0 = blockIdx.y * 32;
    int tx = threadIdx.x, ty = threadIdx.y;
    #pragma unroll
    for (int i = 0; i < 32; i += 8)
        t[ty + i][tx] = W[(size_t)(r0 + ty + i) * C + c0 + tx];
    __syncthreads();
    #pragma unroll
    for (int i = 0; i < 32; i += 8)
        Wt[(size_t)(c0 + ty + i) * R + r0 + tx] = __float2half_rn(t[tx][ty + i]);
}

// batched version for the four D x D matrices; also folds in bias concat
// (z==0, y==0, x<12) and vmean zeroing (z==1, y==0, x<16).
__global__ __launch_bounds__(256) void transpose_cvt4_kernel(
    const float* __restrict__ W0, const float* __restrict__ W1,
    const float* __restrict__ W2, const float* __restrict__ W3,
    __half* __restrict__ T0, __half* __restrict__ T1,
    __half* __restrict__ T2, __half* __restrict__ T3,
    const float* __restrict__ bq, const float* __restrict__ bk,
    const float* __restrict__ bv, float* __restrict__ bqkv,
    float* __restrict__ vmean)
{
    int tx = threadIdx.x, ty = threadIdx.y;
    int ft = ty * 32 + tx;
    if (blockIdx.z == 0 && blockIdx.y == 0 && blockIdx.x < 12) {
        int i = blockIdx.x * 256 + ft;
        float v = (i < D_) ? bq[i] : (i < 2 * D_) ? bk[i - D_] : bv[i - 2 * D_];
        bqkv[i] = v;
    }
    if (blockIdx.z == 1 && blockIdx.y == 0 && blockIdx.x < 16)
        vmean[blockIdx.x * 256 + ft] = 0.f;

    const float* W = (blockIdx.z == 0) ? W0 : (blockIdx.z == 1) ? W1
                   : (blockIdx.z == 2) ? W2 : W3;
    __half* Wt = (blockIdx.z == 0) ? T0 : (blockIdx.z == 1) ? T1
               : (blockIdx.z == 2) ? T2 : T3;
    __shared__ float t[32][33];
    int c0 = blockIdx.x * 32, r0 = blockIdx.y * 32;
    #pragma unroll
    for (int i = 0; i < 32; i += 8)
        t[ty + i][tx] = W[(size_t)(r0 + ty + i) * D_ + c0 + tx];
    __syncthreads();
    #pragma unroll
    for (int i = 0; i < 32; i += 8)
        Wt[(size_t)(c0 + ty + i) * D_ + r0 + tx] = __float2half_rn(t[tx][ty + i]);
}

// ======================= LayerNorm (emits single fp16 plane) ================
__global__ __launch_bounds__(256) void ln_kernel(
    const float* __restrict__ x, const float* __restrict__ gamma,
    const float* __restrict__ beta, __half* __restrict__ oh)
{
    int row = blockIdx.x;
    int tid = threadIdx.x;
    const float* xr = x + (size_t)row * D_;
    float4 v = *(const float4*)(xr + tid * 4);
    float s  = v.x + v.y + v.z + v.w;
    float ss = v.x*v.x + v.y*v.y + v.z*v.z + v.w*v.w;
    #pragma unroll
    for (int o = 16; o > 0; o >>= 1) {
        s  += __shfl_xor_sync(0xffffffffu, s,  o);
        ss += __shfl_xor_sync(0xffffffffu, ss, o);
    }
    __shared__ float2 red[8];
    if ((tid & 31) == 0) red[tid >> 5] = make_float2(s, ss);
    __syncthreads();
    if (tid < 32) {
        float2 r = (tid < 8) ? red[tid] : make_float2(0.f, 0.f);
        s = r.x; ss = r.y;
        #pragma unroll
        for (int o = 4; o > 0; o >>= 1) {
            s  += __shfl_xor_sync(0xffffffffu, s,  o);
            ss += __shfl_xor_sync(0xffffffffu, ss, o);
        }
        if (tid == 0) red[0] = make_float2(s, ss);
    }
    __syncthreads();
    float mu  = red[0].x * (1.0f / D_);
    float var = red[0].y * (1.0f / D_) - mu * mu;
    float inv = rsqrtf(var + 1e-5f);
    float4 g4 = *(const float4*)(gamma + tid * 4);
    float4 b4 = *(const float4*)(beta  + tid * 4);
    float4 o4;
    o4.x = (v.x - mu) * inv * g4.x + b4.x;
    o4.y = (v.y - mu) * inv * g4.y + b4.y;
    o4.z = (v.z - mu) * inv * g4.z + b4.z;
    o4.w = (v.w - mu) * inv * g4.w + b4.w;
    *(uint2*)(oh + (size_t)row * D_ + tid * 4) = cvt_f16(o4);
}

// ======================= HMMA GEMM (fp16; 5-stage cp.async pipeline) ========
#define EPI_BIAS      0
#define EPI_BIAS_RES  1
#define EPI_BIAS_GELU 2

#define ROWB   80u
#define PLANE  (128u * ROWB)      // 10240
#define OFF_A  0u
#define OFF_B  (PLANE)
#define STAGE  (2u * PLANE)       // 20480
#define NSTAGE 5
#define MGEMM_SMEM (NSTAGE * STAGE)  // 102400

template <int EPI, int OUTHALF>
__global__ __launch_bounds__(256) void mgemm_kernel(
    const __half* __restrict__ A, const __half* __restrict__ Bt,
    const float* __restrict__ bias, const float* __restrict__ res,
    float* __restrict__ C, __half* __restrict__ Ch,
    int M, int N, int K)
{
    extern __shared__ __align__(128) char smem[];
    uint32_t sb = smem_u32(smem);
    int tid = threadIdx.x;
    int lane = tid & 31, wid = tid >> 5;
    int wm = wid >> 1, wn = wid & 1;
    int m0 = blockIdx.y * 128, n0 = blockIdx.x * 128;

    uint32_t aOff = (uint32_t)(wm * 32 + (lane & 15)) * ROWB + ((lane >> 4) << 4);
    uint32_t bOff = (uint32_t)(wn * 64 + (lane & 7) + ((lane >> 4) << 3)) * ROWB
                  + (((lane >> 3) & 1) << 4);

    float acc[2][8][4];
    #pragma unroll
    for (int mi = 0; mi < 2; mi++)
        #pragma unroll
        for (int ni = 0; ni < 8; ni++)
            #pragma unroll
            for (int c = 0; c < 4; c++) acc[mi][ni][c] = 0.f;

    int cr[2], cc[2];
    #pragma unroll
    for (int p = 0; p < 2; p++) {
        int idx = tid + p * 256;
        cr[p] = idx >> 2;
        cc[p] = (idx & 3) << 4;
    }

    const int nIter = K >> 5;

    auto load_stage = [&](int stg, int chunk) {
        uint32_t base = sb + (uint32_t)stg * STAGE;
        int k0 = chunk << 5;
        #pragma unroll
        for (int p = 0; p < 2; p++) {
            size_t ga = (size_t)(m0 + cr[p]) * K + k0 + (cc[p] >> 1);
            size_t gb = (size_t)(n0 + cr[p]) * K + k0 + (cc[p] >> 1);
            uint32_t so = (uint32_t)cr[p] * ROWB + (uint32_t)cc[p];
            cp16(base + OFF_A + so, A  + ga);
            cp16(base + OFF_B + so, Bt + gb);
        }
    };

    load_stage(0, 0); CP_COMMIT();
    if (nIter > 1) load_stage(1, 1); CP_COMMIT();
    if (nIter > 2) load_stage(2, 2); CP_COMMIT();
    if (nIter > 3) load_stage(3, 3); CP_COMMIT();

    for (int i = 0; i < nIter; i++) {
        CP_WAIT3();            // stage i landed (<=3 groups outstanding)
        __syncthreads();
        if (i + 4 < nIter) load_stage((i + 4) % NSTAGE, i + 4);
        CP_COMMIT();

        uint32_t st = sb + (uint32_t)(i % NSTAGE) * STAGE;
        #pragma unroll
        for (int ks = 0; ks < 2; ks++) {
            uint32_t ko = (uint32_t)ks * 32;
            uint32_t a[2][4], b[4][4];
            #pragma unroll
            for (int mi = 0; mi < 2; mi++)
                ldsm_x4(a[mi], st + OFF_A + aOff + ko + (uint32_t)mi * 16 * ROWB);
            #pragma unroll
            for (int nj = 0; nj < 4; nj++)
                ldsm_x4(b[nj], st + OFF_B + bOff + ko + (uint32_t)nj * 16 * ROWB);
            #pragma unroll
            for (int mi = 0; mi < 2; mi++) {
                #pragma unroll
                for (int nj = 0; nj < 4; nj++) {
                    mma_f16(acc[mi][2*nj],   a[mi], b[nj][0], b[nj][1]);
                    mma_f16(acc[mi][2*nj+1], a[mi], b[nj][2], b[nj][3]);
                }
            }
        }
    }

    #pragma unroll
    for (int mi = 0; mi < 2; mi++) {
        #pragma unroll
        for (int ni = 0; ni < 8; ni++) {
            int row = m0 + wm * 32 + mi * 16 + (lane >> 2);
            int col = n0 + wn * 64 + ni * 8 + ((lane & 3) << 1);
            float* c = acc[mi][ni];
            float2 bi = *(const float2*)(bias + col);
            float2 o0 = make_float2(c[0] + bi.x, c[1] + bi.y);
            float2 o1 = make_float2(c[2] + bi.x, c[3] + bi.y);
            if (EPI == EPI_BIAS_RES) {
                float2 r0 = *(const float2*)(res + (size_t)row * N + col);
                float2 r1 = *(const float2*)(res + (size_t)(row + 8) * N + col);
                o0.x += r0.x; o0.y += r0.y; o1.x += r1.x; o1.y += r1.y;
            } else if (EPI == EPI_BIAS_GELU) {
                o0.x = gelu_exact(o0.x); o0.y = gelu_exact(o0.y);
                o1.x = gelu_exact(o1.x); o1.y = gelu_exact(o1.y);
            }
            if (OUTHALF) {
                *(uint32_t*)(Ch + (size_t)row * N + col)       = pack2_f16(o0.x, o0.y);
                *(uint32_t*)(Ch + (size_t)(row + 8) * N + col) = pack2_f16(o1.x, o1.y);
            } else {
                *(float2*)(C + (size_t)row * N + col)       = o0;
                *(float2*)(C + (size_t)(row + 8) * N + col) = o1;
            }
        }
    }
}

// ---------------- V column means (V lives in qkv at offset 2*D_) ------------
__global__ void vmean_acc(const __half* __restrict__ qkv, float* __restrict__ vmean) {
    int b = blockIdx.x, chunk = blockIdx.y, d = threadIdx.x;
    int s0 = chunk * 256;
    float s = 0.f;
    for (int i = 0; i < 256; i++)
        s += __half2float(qkv[(size_t)(b * S_ + s0 + i) * LD3 + 2 * D_ + d]);
    atomicAdd(&vmean[b * D_ + d], s * (1.0f / S_));
}

// ======================= HMMA flash attention (fp16, 1-pass, dbl-buffered) ==
// 128 queries/block (8 warps x 16 rows), 64-key tiles, dk=64.
// K/V double-buffered in smem with register prefetch; one sync per tile.
#define AROWB    144u
#define KVSTAGE  (2u * 64u * AROWB)   // K + V^T per stage = 18432
#define AQ_OFF   (2u * KVSTAGE)       // 36864
#define ATT2_SMEM (AQ_OFF + 64u * 144u * 2u)  // + Q tile (128 rows x 144B) = 55296

__global__ void __launch_bounds__(256, 2) attn2_kernel(
    const __half* __restrict__ qkv, const int* __restrict__ mask,
    const float* __restrict__ vmean, __half* __restrict__ ctx)
{
    extern __shared__ __align__(128) char sm[];
    __shared__ int msk[2][64];
    uint32_t sb = smem_u32(sm);
    int tid = threadIdx.x, lane = tid & 31, wid = tid >> 5;
    int bh = blockIdx.y, b = bh >> 4, h = bh & 15;
    int q0 = blockIdx.x << 7;

    // per-thread K/V load coords (4 iterations of 256 threads over 64x16 uint2)
    int krr[4], kcc[4];
    #pragma unroll
    for (int p = 0; p < 4; p++) {
        int idx = tid + p * 256;
        krr[p] = idx >> 4;            // row 0..63
        kcc[p] = (idx & 15) << 2;     // col elem 0..60
    }

    auto store_kv = [&](int stg, const uint2* kv_, const uint2* vv_, int pm) {
        uint32_t base = (uint32_t)stg * KVSTAGE;
        #pragma unroll
        for (int p = 0; p < 4; p++) {
            *(uint2*)(sm + base + (uint32_t)krr[p] * AROWB + (uint32_t)kcc[p] * 2) = kv_[p];
            __half2 v01 = *(__half2*)&vv_[p].x;
            __half2 v23 = *(__half2*)&vv_[p].y;
            uint32_t tbase = base + 64u * AROWB + (uint32_t)kcc[p] * AROWB + (uint32_t)krr[p] * 2;
            *(__half*)(sm + tbase)             = v01.x;
            *(__half*)(sm + tbase + AROWB)     = v01.y;
            *(__half*)(sm + tbase + 2 * AROWB) = v23.x;
            *(__half*)(sm + tbase + 3 * AROWB) = v23.y;
        }
        if (tid < 64) msk[stg][tid] = pm;
    };
    auto load_kv_regs = [&](int k0, uint2* kv_, uint2* vv_, int& pm) {
        #pragma unroll
        for (int p = 0; p < 4; p++) {
            size_t gbase = (size_t)(b * S_ + k0 + krr[p]) * LD3 + h * DK_ + kcc[p];
            kv_[p] = *(const uint2*)(qkv + gbase + D_);
            vv_[p] = *(const uint2*)(qkv + gbase + 2 * D_);
        }
        if (tid < 64) pm = mask[b * S_ + k0 + tid];
    };

    // ---- stage Q tile + tile-0 K/V ----
    #pragma unroll
    for (int p = 0; p < 8; p++) {
        int idx = tid + p * 256;
        int r = idx >> 4, c4 = (idx & 15) << 2;
        *(uint2*)(sm + AQ_OFF + (uint32_t)r * AROWB + (uint32_t)c4 * 2) =
            *(const uint2*)(qkv + (size_t)(b * S_ + q0 + r) * LD3 + h * DK_ + c4);
    }
    {
        uint2 kv0[4], vv0[4]; int pm0;
        load_kv_regs(0, kv0, vv0, pm0);
        store_kv(0, kv0, vv0, pm0);
    }
    __syncthreads();

    uint32_t aOff = (uint32_t)(wid * 16 + (lane & 15)) * AROWB + ((lane >> 4) << 4);
    uint32_t qf[4][4];
    #pragma unroll
    for (int ks = 0; ks < 4; ks++)
        ldsm_x4(qf[ks], sb + AQ_OFF + aOff + (uint32_t)ks * 32);

    float o[8][4];
    #pragma unroll
    for (int jf = 0; jf < 8; jf++)
        #pragma unroll
        for (int c = 0; c < 4; c++) o[jf][c] = 0.f;
    float m0 = -3.0e38f, m1 = -3.0e38f, l0 = 0.f, l1 = 0.f;

    uint32_t bOff = (uint32_t)((lane & 7) + ((lane >> 4) << 3)) * AROWB
                  + (((lane >> 3) & 1) << 4);

    const int rq0 = q0 + wid * 16 + (lane >> 2);
    const int rq1 = rq0 + 8;
    const int colb = (lane & 3) << 1;

    int jmax = (q0 + 127) >> 6;
    for (int j = 0; j <= jmax; j++) {
        int k0 = j << 6;
        int cur = j & 1;
        uint32_t kbase = sb + (uint32_t)cur * KVSTAGE;
        uint32_t vbase = kbase + 64u * AROWB;

        // prefetch next tile into registers
        uint2 pk[4], pv[4]; int pm = 0;
        if (j < jmax) load_kv_regs(k0 + 64, pk, pv, pm);

        // ---- QK^T (1-pass fp16) ----
        float s[8][4];
        #pragma unroll
        for (int jf = 0; jf < 8; jf++)
            #pragma unroll
            for (int c = 0; c < 4; c++) s[jf][c] = 0.f;
        #pragma unroll
        for (int ks = 0; ks < 4; ks++) {
            #pragma unroll
            for (int nj = 0; nj < 4; nj++) {
                uint32_t kk[4];
                uint32_t off = bOff + (uint32_t)nj * 16 * AROWB + (uint32_t)ks * 32;
                ldsm_x4(kk, kbase + off);
                mma_f16(s[2*nj],   qf[ks], kk[0], kk[1]);
                mma_f16(s[2*nj+1], qf[ks], kk[2], kk[3]);
            }
        }
        #pragma unroll
        for (int jf = 0; jf < 8; jf++) {
            s[jf][0] *= 0.125f; s[jf][1] *= 0.125f;
            s[jf][2] *= 0.125f; s[jf][3] *= 0.125f;
        }

        // ---- mask (causal + padding); exact -1e9 to match reference ----
        #pragma unroll
        for (int jf = 0; jf < 8; jf++) {
            int col = jf * 8 + colb;
            int kg = k0 + col;
            int mk0 = msk[cur][col], mk1 = msk[cur][col + 1];
            if (kg > rq0     || mk0 == 0) s[jf][0] = -1.0e9f;
            if (kg + 1 > rq0 || mk1 == 0) s[jf][1] = -1.0e9f;
            if (kg > rq1     || mk0 == 0) s[jf][2] = -1.0e9f;
            if (kg + 1 > rq1 || mk1 == 0) s[jf][3] = -1.0e9f;
        }

        // ---- online softmax ----
        float mt0 = -3.0e38f, mt1 = -3.0e38f;
        #pragma unroll
        for (int jf = 0; jf < 8; jf++) {
            mt0 = fmaxf(mt0, fmaxf(s[jf][0], s[jf][1]));
            mt1 = fmaxf(mt1, fmaxf(s[jf][2], s[jf][3]));
        }
        mt0 = fmaxf(mt0, __shfl_xor_sync(0xffffffffu, mt0, 1));
        mt0 = fmaxf(mt0, __shfl_xor_sync(0xffffffffu, mt0, 2));
        mt1 = fmaxf(mt1, __shfl_xor_sync(0xffffffffu, mt1, 1));
        mt1 = fmaxf(mt1, __shfl_xor_sync(0xffffffffu, mt1, 2));
        float mn0 = fmaxf(m0, mt0), mn1 = fmaxf(m1, mt1);
        float sc0 = __expf(m0 - mn0), sc1 = __expf(m1 - mn1);
        float ls0 = 0.f, ls1 = 0.f;
        #pragma unroll
        for (int jf = 0; jf < 8; jf++) {
            s[jf][0] = __expf(s[jf][0] - mn0);
            s[jf][1] = __expf(s[jf][1] - mn0);
            s[jf][2] = __expf(s[jf][2] - mn1);
            s[jf][3] = __expf(s[jf][3] - mn1);
            ls0 += s[jf][0] + s[jf][1];
            ls1 += s[jf][2] + s[jf][3];
        }
        ls0 += __shfl_xor_sync(0xffffffffu, ls0, 1);
        ls0 += __shfl_xor_sync(0xffffffffu, ls0, 2);
        ls1 += __shfl_xor_sync(0xffffffffu, ls1, 1);
        ls1 += __shfl_xor_sync(0xffffffffu, ls1, 2);
        l0 = l0 * sc0 + ls0;
        l1 = l1 * sc1 + ls1;
        m0 = mn0; m1 = mn1;
        #pragma unroll
        for (int jf = 0; jf < 8; jf++) {
            o[jf][0] *= sc0; o[jf][1] *= sc0;
            o[jf][2] *= sc1; o[jf][3] *= sc1;
        }

        // ---- P @ V (P single fp16; 1-pass) ----
        #pragma unroll
        for (int ks = 0; ks < 4; ks++) {
            uint32_t ph[4];
            ph[0] = pack2_f16(s[2*ks][0],   s[2*ks][1]);
            ph[1] = pack2_f16(s[2*ks][2],   s[2*ks][3]);
            ph[2] = pack2_f16(s[2*ks+1][0], s[2*ks+1][1]);
            ph[3] = pack2_f16(s[2*ks+1][2], s[2*ks+1][3]);
            #pragma unroll
            for (int nj = 0; nj < 4; nj++) {
                uint32_t vv[4];
                uint32_t off = bOff + (uint32_t)nj * 16 * AROWB + (uint32_t)ks * 32;
                ldsm_x4(vv, vbase + off);
                mma_f16(o[2*nj],   ph, vv[0], vv[1]);
                mma_f16(o[2*nj+1], ph, vv[2], vv[3]);
            }
        }

        // ---- store prefetched tile into alternate stage ----
        if (j < jmax) {
            store_kv(cur ^ 1, pk, pv, pm);
            __syncthreads();
        }
    }

    // ---- epilogue: write ctx as single fp16 plane ----
    float inv0 = 1.0f / l0, inv1 = 1.0f / l1;
    bool dg0 = (m0 < -1.0e8f), dg1 = (m1 < -1.0e8f);
    #pragma unroll
    for (int jf = 0; jf < 8; jf++) {
        int col = h * DK_ + jf * 8 + colb;
        const float* vm = vmean + b * D_ + col;
        float2 w0, w1;
        w0.x = dg0 ? vm[0] : o[jf][0] * inv0;
        w0.y = dg0 ? vm[1] : o[jf][1] * inv0;
        w1.x = dg1 ? vm[0] : o[jf][2] * inv1;
        w1.y = dg1 ? vm[1] : o[jf][3] * inv1;
        *(uint32_t*)(ctx + (size_t)(b * S_ + rq0) * D_ + col) = pack2_f16(w0.x, w0.y);
        *(uint32_t*)(ctx + (size_t)(b * S_ + rq1) * D_ + col) = pack2_f16(w1.x, w1.y);
    }
}

// ---------------- launch ---------------------------------------------------
extern "C" void kernel_launch(void* const* d_in, const int* in_sizes, int n_in,
                              void* d_out, int out_size)
{
    (void)in_sizes; (void)n_in; (void)out_size;
    const float* x     = (const float*)d_in[0];
    const int*   amask = (const int*)  d_in[1];
    const float* Wq = (const float*)d_in[2];  const float* bq = (const float*)d_in[3];
    const float* Wk = (const float*)d_in[4];  const float* bk = (const float*)d_in[5];
    const float* Wv = (const float*)d_in[6];  const float* bv = (const float*)d_in[7];
    const float* Wo = (const float*)d_in[8];  const float* bo = (const float*)d_in[9];
    const float* W1 = (const float*)d_in[10]; const float* b1 = (const float*)d_in[11];
    const float* W2 = (const float*)d_in[12]; const float* b2 = (const float*)d_in[13];
    const float* g1 = (const float*)d_in[14]; const float* be1 = (const float*)d_in[15];
    const float* g2 = (const float*)d_in[16]; const float* be2 = (const float*)d_in[17];
    float* out = (float*)d_out;

    float *vmean, *bqkv;
    __half *hb, *qkv, *ctx, *a;
    __half *wqkvt, *wot, *w1t, *w2t;
    cudaGetSymbolAddress((void**)&vmean, g_vmean);
    cudaGetSymbolAddress((void**)&bqkv,  g_bqkv);
    cudaGetSymbolAddress((void**)&hb,    g_h);
    cudaGetSymbolAddress((void**)&qkv,   g_qkv);
    cudaGetSymbolAddress((void**)&ctx,   g_ctx);
    cudaGetSymbolAddress((void**)&a,     g_a);
    cudaGetSymbolAddress((void**)&wqkvt, g_wqkvt);
    cudaGetSymbolAddress((void**)&wot,   g_wot);
    cudaGetSymbolAddress((void**)&w1t,   g_w1t);
    cudaGetSymbolAddress((void**)&w2t,   g_w2t);

    cudaFuncSetAttribute(attn2_kernel, cudaFuncAttributeMaxDynamicSharedMemorySize, ATT2_SMEM);
    cudaFuncSetAttribute(mgemm_kernel<EPI_BIAS, 1>,      cudaFuncAttributeMaxDynamicSharedMemorySize, MGEMM_SMEM);
    cudaFuncSetAttribute(mgemm_kernel<EPI_BIAS_RES, 0>,  cudaFuncAttributeMaxDynamicSharedMemorySize, MGEMM_SMEM);
    cudaFuncSetAttribute(mgemm_kernel<EPI_BIAS_GELU, 1>, cudaFuncAttributeMaxDynamicSharedMemorySize, MGEMM_SMEM);

    dim3 tb(32, 8);
    transpose_cvt4_kernel<<<dim3(D_ / 32, D_ / 32, 4), tb>>>(
        Wq, Wk, Wv, Wo,
        wqkvt, wqkvt + (size_t)D_ * D_, wqkvt + (size_t)2 * D_ * D_, wot,
        bq, bk, bv, bqkv, vmean);
    transpose_cvt_kernel<<<dim3(F_ / 32, D_ / 32), tb>>>(W1, w1t, D_, F_);
    transpose_cvt_kernel<<<dim3(D_ / 32, F_ / 32), tb>>>(W2, w2t, F_, D_);

    dim3 gD(D_ / 128, NTOK / 128);     // (8, 64)
    dim3 gQKV(LD3 / 128, NTOK / 128);  // (24, 64)
    dim3 gF(F_ / 128, NTOK / 128);     // (32, 64)

    // attention sublayer (pre-norm)
    ln_kernel<<<NTOK, 256>>>(x, g1, be1, hb);
    mgemm_kernel<EPI_BIAS, 1><<<gQKV, 256, MGEMM_SMEM>>>(hb, wqkvt, bqkv, nullptr, nullptr, qkv, NTOK, LD3, D_);
    vmean_acc<<<dim3(4, 8), 1024>>>(qkv, vmean);
    attn2_kernel<<<dim3(S_ / 128, B_ * H_), 256, ATT2_SMEM>>>(qkv, amask, vmean, ctx);
    mgemm_kernel<EPI_BIAS_RES, 0><<<gD, 256, MGEMM_SMEM>>>(ctx, wot, bo, x, out, nullptr, NTOK, D_, D_);

    // FFN sublayer (pre-norm)
    ln_kernel<<<NTOK, 256>>>(out, g2, be2, hb);
    mgemm_kernel<EPI_BIAS_GELU, 1><<<gF, 256, MGEMM_SMEM>>>(hb, w1t, b1, nullptr, nullptr, a, NTOK, F_, D_);
    mgemm_kernel<EPI_BIAS_RES, 0><<<gD, 256, MGEMM_SMEM>>>(a, w2t, b2, out, out, nullptr, NTOK, D_, F_);
}

// round 14
// speedup vs baseline: 1.0340x; 1.0340x over previous
#include <cuda_runtime.h>
#include <cuda_fp16.h>
#include <math.h>
#include <stdint.h>

#define B_   4
#define S_   2048
#define D_   1024
#define H_   16
#define DK_  64
#define F_   4096
#define NTOK (B_ * S_)
#define LD3  (3 * D_)

// ---------------- scratch (device globals: no allocation allowed) ----------
__device__ __half g_h[(size_t)NTOK * D_];
__device__ __half g_qkv[(size_t)NTOK * LD3];   // q | k | v interleaved per row
__device__ __half g_ctx[(size_t)NTOK * D_];
__device__ __half g_a[(size_t)NTOK * F_];
__device__ float  g_vmean[B_ * D_];
__device__ float  g_bqkv[LD3];
// transposed fp16 weights [N, K], single plane
__device__ __half g_wqkvt[(size_t)LD3 * D_];   // Wq^T | Wk^T | Wv^T stacked
__device__ __half g_wot[(size_t)D_ * D_];
__device__ __half g_w1t[(size_t)F_ * D_];
__device__ __half g_w2t[(size_t)D_ * F_];

// ======================= helpers ============================================
__device__ __forceinline__ uint32_t smem_u32(const void* p) {
    uint32_t a;
    asm("{ .reg .u64 t; cvta.to.shared.u64 t, %1; cvt.u32.u64 %0, t; }"
        : "=r"(a) : "l"(p));
    return a;
}

__device__ __forceinline__ void ldsm_x4(uint32_t* r, uint32_t addr) {
    asm volatile("ldmatrix.sync.aligned.m8n8.x4.shared.b16 {%0,%1,%2,%3}, [%4];"
        : "=r"(r[0]), "=r"(r[1]), "=r"(r[2]), "=r"(r[3]) : "r"(addr));
}

__device__ __forceinline__ void mma_f16(float* c, const uint32_t* a,
                                        uint32_t b0, uint32_t b1) {
    asm volatile(
        "mma.sync.aligned.m16n8k16.row.col.f32.f16.f16.f32 "
        "{%0,%1,%2,%3}, {%4,%5,%6,%7}, {%8,%9}, {%0,%1,%2,%3};"
        : "+f"(c[0]), "+f"(c[1]), "+f"(c[2]), "+f"(c[3])
        : "r"(a[0]), "r"(a[1]), "r"(a[2]), "r"(a[3]), "r"(b0), "r"(b1));
}

__device__ __forceinline__ void cp16(uint32_t dst, const void* src) {
    asm volatile("cp.async.cg.shared.global [%0], [%1], 16;" :: "r"(dst), "l"(src));
}
#define CP_COMMIT() asm volatile("cp.async.commit_group;" ::: "memory")
#define CP_WAIT2()  asm volatile("cp.async.wait_group 2;" ::: "memory")

__device__ __forceinline__ uint2 cvt_f16(float4 v) {
    __half2 h01 = __floats2half2_rn(v.x, v.y);
    __half2 h23 = __floats2half2_rn(v.z, v.w);
    return make_uint2(*(uint32_t*)&h01, *(uint32_t*)&h23);
}
__device__ __forceinline__ uint32_t pack2_f16(float a, float b) {
    __half2 h = __floats2half2_rn(a, b);
    return *(uint32_t*)&h;
}

__device__ __forceinline__ float gelu_exact(float x) {
    return 0.5f * x * (1.0f + erff(x * 0.70710678118654752f));
}

// ======================= weight transpose + fp16 cvt ========================
__global__ __launch_bounds__(256) void transpose_cvt_kernel(
    const float* __restrict__ W, __half* __restrict__ Wt, int R, int C)
{
    __shared__ float t[32][33];
    int c0 = blockIdx.x * 32, r0 = blockIdx.y * 32;
    int tx = threadIdx.x, ty = threadIdx.y;
    #pragma unroll
    for (int i = 0; i < 32; i += 8)
        t[ty + i][tx] = W[(size_t)(r0 + ty + i) * C + c0 + tx];
    __syncthreads();
    #pragma unroll
    for (int i = 0; i < 32; i += 8)
        Wt[(size_t)(c0 + ty + i) * R + r0 + tx] = __float2half_rn(t[tx][ty + i]);
}

// batched version for the four D x D matrices; also folds in bias concat
// (z==0, y==0, x<12) and vmean zeroing (z==1, y==0, x<16).
__global__ __launch_bounds__(256) void transpose_cvt4_kernel(
    const float* __restrict__ W0, const float* __restrict__ W1,
    const float* __restrict__ W2, const float* __restrict__ W3,
    __half* __restrict__ T0, __half* __restrict__ T1,
    __half* __restrict__ T2, __half* __restrict__ T3,
    const float* __restrict__ bq, const float* __restrict__ bk,
    const float* __restrict__ bv, float* __restrict__ bqkv,
    float* __restrict__ vmean)
{
    int tx = threadIdx.x, ty = threadIdx.y;
    int ft = ty * 32 + tx;
    if (blockIdx.z == 0 && blockIdx.y == 0 && blockIdx.x < 12) {
        int i = blockIdx.x * 256 + ft;
        float v = (i < D_) ? bq[i] : (i < 2 * D_) ? bk[i - D_] : bv[i - 2 * D_];
        bqkv[i] = v;
    }
    if (blockIdx.z == 1 && blockIdx.y == 0 && blockIdx.x < 16)
        vmean[blockIdx.x * 256 + ft] = 0.f;

    const float* W = (blockIdx.z == 0) ? W0 : (blockIdx.z == 1) ? W1
                   : (blockIdx.z == 2) ? W2 : W3;
    __half* Wt = (blockIdx.z == 0) ? T0 : (blockIdx.z == 1) ? T1
               : (blockIdx.z == 2) ? T2 : T3;
    __shared__ float t[32][33];
    int c0 = blockIdx.x * 32, r0 = blockIdx.y * 32;
    #pragma unroll
    for (int i = 0; i < 32; i += 8)
        t[ty + i][tx] = W[(size_t)(r0 + ty + i) * D_ + c0 + tx];
    __syncthreads();
    #pragma unroll
    for (int i = 0; i < 32; i += 8)
        Wt[(size_t)(c0 + ty + i) * D_ + r0 + tx] = __float2half_rn(t[tx][ty + i]);
}

// ======================= LayerNorm (warp per row, no barriers) ==============
__global__ __launch_bounds__(256) void ln_kernel(
    const float* __restrict__ x, const float* __restrict__ gamma,
    const float* __restrict__ beta, __half* __restrict__ oh)
{
    int row  = blockIdx.x * 8 + (threadIdx.x >> 5);
    int lane = threadIdx.x & 31;
    const float* xr = x + (size_t)row * D_;

    float4 v[8];
    float s = 0.f, ss = 0.f;
    #pragma unroll
    for (int i = 0; i < 8; i++) {
        v[i] = *(const float4*)(xr + (i * 32 + lane) * 4);
        s  += v[i].x + v[i].y + v[i].z + v[i].w;
        ss += v[i].x * v[i].x + v[i].y * v[i].y
            + v[i].z * v[i].z + v[i].w * v[i].w;
    }
    #pragma unroll
    for (int o = 16; o > 0; o >>= 1) {
        s  += __shfl_xor_sync(0xffffffffu, s,  o);
        ss += __shfl_xor_sync(0xffffffffu, ss, o);
    }
    float mu  = s  * (1.0f / D_);
    float var = ss * (1.0f / D_) - mu * mu;
    float inv = rsqrtf(var + 1e-5f);

    #pragma unroll
    for (int i = 0; i < 8; i++) {
        int c = (i * 32 + lane) * 4;
        float4 g4 = *(const float4*)(gamma + c);
        float4 b4 = *(const float4*)(beta  + c);
        float4 o4;
        o4.x = (v[i].x - mu) * inv * g4.x + b4.x;
        o4.y = (v[i].y - mu) * inv * g4.y + b4.y;
        o4.z = (v[i].z - mu) * inv * g4.z + b4.z;
        o4.w = (v[i].w - mu) * inv * g4.w + b4.w;
        *(uint2*)(oh + (size_t)row * D_ + c) = cvt_f16(o4);
    }
}

// ======================= HMMA GEMM (fp16; 4-stage cp.async pipeline) ========
#define EPI_BIAS      0
#define EPI_BIAS_RES  1
#define EPI_BIAS_GELU 2

#define ROWB   80u
#define PLANE  (128u * ROWB)      // 10240
#define OFF_A  0u
#define OFF_B  (PLANE)
#define STAGE  (2u * PLANE)       // 20480
#define NSTAGE 4
#define MGEMM_SMEM (NSTAGE * STAGE)  // 81920

template <int EPI, int OUTHALF>
__global__ __launch_bounds__(256) void mgemm_kernel(
    const __half* __restrict__ A, const __half* __restrict__ Bt,
    const float* __restrict__ bias, const float* __restrict__ res,
    float* __restrict__ C, __half* __restrict__ Ch,
    int M, int N, int K)
{
    extern __shared__ __align__(128) char smem[];
    uint32_t sb = smem_u32(smem);
    int tid = threadIdx.x;
    int lane = tid & 31, wid = tid >> 5;
    int wm = wid >> 1, wn = wid & 1;
    int m0 = blockIdx.y * 128, n0 = blockIdx.x * 128;

    uint32_t aOff = (uint32_t)(wm * 32 + (lane & 15)) * ROWB + ((lane >> 4) << 4);
    uint32_t bOff = (uint32_t)(wn * 64 + (lane & 7) + ((lane >> 4) << 3)) * ROWB
                  + (((lane >> 3) & 1) << 4);

    float acc[2][8][4];
    #pragma unroll
    for (int mi = 0; mi < 2; mi++)
        #pragma unroll
        for (int ni = 0; ni < 8; ni++)
            #pragma unroll
            for (int c = 0; c < 4; c++) acc[mi][ni][c] = 0.f;

    int cr[2], cc[2];
    #pragma unroll
    for (int p = 0; p < 2; p++) {
        int idx = tid + p * 256;
        cr[p] = idx >> 2;
        cc[p] = (idx & 3) << 4;
    }

    const int nIter = K >> 5;

    auto load_stage = [&](int stg, int chunk) {
        uint32_t base = sb + (uint32_t)stg * STAGE;
        int k0 = chunk << 5;
        #pragma unroll
        for (int p = 0; p < 2; p++) {
            size_t ga = (size_t)(m0 + cr[p]) * K + k0 + (cc[p] >> 1);
            size_t gb = (size_t)(n0 + cr[p]) * K + k0 + (cc[p] >> 1);
            uint32_t so = (uint32_t)cr[p] * ROWB + (uint32_t)cc[p];
            cp16(base + OFF_A + so, A  + ga);
            cp16(base + OFF_B + so, Bt + gb);
        }
    };

    load_stage(0, 0); CP_COMMIT();
    if (nIter > 1) load_stage(1, 1); CP_COMMIT();
    if (nIter > 2) load_stage(2, 2); CP_COMMIT();

    for (int i = 0; i < nIter; i++) {
        CP_WAIT2();
        __syncthreads();
        if (i + 3 < nIter) load_stage((i + 3) % NSTAGE, i + 3);
        CP_COMMIT();

        uint32_t st = sb + (uint32_t)(i % NSTAGE) * STAGE;
        #pragma unroll
        for (int ks = 0; ks < 2; ks++) {
            uint32_t ko = (uint32_t)ks * 32;
            uint32_t a[2][4], b[4][4];
            #pragma unroll
            for (int mi = 0; mi < 2; mi++)
                ldsm_x4(a[mi], st + OFF_A + aOff + ko + (uint32_t)mi * 16 * ROWB);
            #pragma unroll
            for (int nj = 0; nj < 4; nj++)
                ldsm_x4(b[nj], st + OFF_B + bOff + ko + (uint32_t)nj * 16 * ROWB);
            #pragma unroll
            for (int mi = 0; mi < 2; mi++) {
                #pragma unroll
                for (int nj = 0; nj < 4; nj++) {
                    mma_f16(acc[mi][2*nj],   a[mi], b[nj][0], b[nj][1]);
                    mma_f16(acc[mi][2*nj+1], a[mi], b[nj][2], b[nj][3]);
                }
            }
        }
    }

    #pragma unroll
    for (int mi = 0; mi < 2; mi++) {
        #pragma unroll
        for (int ni = 0; ni < 8; ni++) {
            int row = m0 + wm * 32 + mi * 16 + (lane >> 2);
            int col = n0 + wn * 64 + ni * 8 + ((lane & 3) << 1);
            float* c = acc[mi][ni];
            float2 bi = *(const float2*)(bias + col);
            float2 o0 = make_float2(c[0] + bi.x, c[1] + bi.y);
            float2 o1 = make_float2(c[2] + bi.x, c[3] + bi.y);
            if (EPI == EPI_BIAS_RES) {
                float2 r0 = *(const float2*)(res + (size_t)row * N + col);
                float2 r1 = *(const float2*)(res + (size_t)(row + 8) * N + col);
                o0.x += r0.x; o0.y += r0.y; o1.x += r1.x; o1.y += r1.y;
            } else if (EPI == EPI_BIAS_GELU) {
                o0.x = gelu_exact(o0.x); o0.y = gelu_exact(o0.y);
                o1.x = gelu_exact(o1.x); o1.y = gelu_exact(o1.y);
            }
            if (OUTHALF) {
                *(uint32_t*)(Ch + (size_t)row * N + col)       = pack2_f16(o0.x, o0.y);
                *(uint32_t*)(Ch + (size_t)(row + 8) * N + col) = pack2_f16(o1.x, o1.y);
            } else {
                *(float2*)(C + (size_t)row * N + col)       = o0;
                *(float2*)(C + (size_t)(row + 8) * N + col) = o1;
            }
        }
    }
}

// ---------------- V column means (V lives in qkv at offset 2*D_) ------------
__global__ void vmean_acc(const __half* __restrict__ qkv, float* __restrict__ vmean) {
    int b = blockIdx.x, chunk = blockIdx.y, d = threadIdx.x;
    int s0 = chunk * 256;
    float s = 0.f;
    for (int i = 0; i < 256; i++)
        s += __half2float(qkv[(size_t)(b * S_ + s0 + i) * LD3 + 2 * D_ + d]);
    atomicAdd(&vmean[b * D_ + d], s * (1.0f / S_));
}

// ======================= HMMA flash attention (fp16, 1-pass, dbl-buffered) ==
// 128 queries/block (8 warps x 16 rows), 64-key tiles, dk=64.
// K/V double-buffered in smem with register prefetch; one sync per tile.
#define AROWB    144u
#define KVSTAGE  (2u * 64u * AROWB)   // K + V^T per stage = 18432
#define AQ_OFF   (2u * KVSTAGE)       // 36864
#define ATT2_SMEM (AQ_OFF + 64u * 144u * 2u)  // + Q tile (128 rows x 144B) = 55296

__global__ void __launch_bounds__(256, 1) attn2_kernel(
    const __half* __restrict__ qkv, const int* __restrict__ mask,
    const float* __restrict__ vmean, __half* __restrict__ ctx)
{
    extern __shared__ __align__(128) char sm[];
    __shared__ int msk[2][64];
    uint32_t sb = smem_u32(sm);
    int tid = threadIdx.x, lane = tid & 31, wid = tid >> 5;
    int bh = blockIdx.y, b = bh >> 4, h = bh & 15;
    int q0 = blockIdx.x << 7;

    // per-thread K/V load coords (4 iterations of 256 threads over 64x16 uint2)
    int krr[4], kcc[4];
    #pragma unroll
    for (int p = 0; p < 4; p++) {
        int idx = tid + p * 256;
        krr[p] = idx >> 4;            // row 0..63
        kcc[p] = (idx & 15) << 2;     // col elem 0..60
    }

    auto store_kv = [&](int stg, const uint2* kv_, const uint2* vv_, int pm) {
        uint32_t base = (uint32_t)stg * KVSTAGE;
        #pragma unroll
        for (int p = 0; p < 4; p++) {
            *(uint2*)(sm + base + (uint32_t)krr[p] * AROWB + (uint32_t)kcc[p] * 2) = kv_[p];
            __half2 v01 = *(__half2*)&vv_[p].x;
            __half2 v23 = *(__half2*)&vv_[p].y;
            uint32_t tbase = base + 64u * AROWB + (uint32_t)kcc[p] * AROWB + (uint32_t)krr[p] * 2;
            *(__half*)(sm + tbase)             = v01.x;
            *(__half*)(sm + tbase + AROWB)     = v01.y;
            *(__half*)(sm + tbase + 2 * AROWB) = v23.x;
            *(__half*)(sm + tbase + 3 * AROWB) = v23.y;
        }
        if (tid < 64) msk[stg][tid] = pm;
    };
    auto load_kv_regs = [&](int k0, uint2* kv_, uint2* vv_, int& pm) {
        #pragma unroll
        for (int p = 0; p < 4; p++) {
            size_t gbase = (size_t)(b * S_ + k0 + krr[p]) * LD3 + h * DK_ + kcc[p];
            kv_[p] = *(const uint2*)(qkv + gbase + D_);
            vv_[p] = *(const uint2*)(qkv + gbase + 2 * D_);
        }
        if (tid < 64) pm = mask[b * S_ + k0 + tid];
    };

    // ---- stage Q tile + tile-0 K/V ----
    #pragma unroll
    for (int p = 0; p < 8; p++) {
        int idx = tid + p * 256;
        int r = idx >> 4, c4 = (idx & 15) << 2;
        *(uint2*)(sm + AQ_OFF + (uint32_t)r * AROWB + (uint32_t)c4 * 2) =
            *(const uint2*)(qkv + (size_t)(b * S_ + q0 + r) * LD3 + h * DK_ + c4);
    }
    {
        uint2 kv0[4], vv0[4]; int pm0;
        load_kv_regs(0, kv0, vv0, pm0);
        store_kv(0, kv0, vv0, pm0);
    }
    __syncthreads();

    uint32_t aOff = (uint32_t)(wid * 16 + (lane & 15)) * AROWB + ((lane >> 4) << 4);
    uint32_t qf[4][4];
    #pragma unroll
    for (int ks = 0; ks < 4; ks++)
        ldsm_x4(qf[ks], sb + AQ_OFF + aOff + (uint32_t)ks * 32);

    float o[8][4];
    #pragma unroll
    for (int jf = 0; jf < 8; jf++)
        #pragma unroll
        for (int c = 0; c < 4; c++) o[jf][c] = 0.f;
    float m0 = -3.0e38f, m1 = -3.0e38f, l0 = 0.f, l1 = 0.f;

    uint32_t bOff = (uint32_t)((lane & 7) + ((lane >> 4) << 3)) * AROWB
                  + (((lane >> 3) & 1) << 4);

    const int rq0 = q0 + wid * 16 + (lane >> 2);
    const int rq1 = rq0 + 8;
    const int colb = (lane & 3) << 1;

    int jmax = (q0 + 127) >> 6;
    for (int j = 0; j <= jmax; j++) {
        int k0 = j << 6;
        int cur = j & 1;
        uint32_t kbase = sb + (uint32_t)cur * KVSTAGE;
        uint32_t vbase = kbase + 64u * AROWB;

        // prefetch next tile into registers
        uint2 pk[4], pv[4]; int pm = 0;
        if (j < jmax) load_kv_regs(k0 + 64, pk, pv, pm);

        // ---- QK^T (1-pass fp16) ----
        float s[8][4];
        #pragma unroll
        for (int jf = 0; jf < 8; jf++)
            #pragma unroll
            for (int c = 0; c < 4; c++) s[jf][c] = 0.f;
        #pragma unroll
        for (int ks = 0; ks < 4; ks++) {
            #pragma unroll
            for (int nj = 0; nj < 4; nj++) {
                uint32_t kk[4];
                uint32_t off = bOff + (uint32_t)nj * 16 * AROWB + (uint32_t)ks * 32;
                ldsm_x4(kk, kbase + off);
                mma_f16(s[2*nj],   qf[ks], kk[0], kk[1]);
                mma_f16(s[2*nj+1], qf[ks], kk[2], kk[3]);
            }
        }
        #pragma unroll
        for (int jf = 0; jf < 8; jf++) {
            s[jf][0] *= 0.125f; s[jf][1] *= 0.125f;
            s[jf][2] *= 0.125f; s[jf][3] *= 0.125f;
        }

        // ---- mask (causal + padding); exact -1e9 to match reference ----
        #pragma unroll
        for (int jf = 0; jf < 8; jf++) {
            int col = jf * 8 + colb;
            int kg = k0 + col;
            int mk0 = msk[cur][col], mk1 = msk[cur][col + 1];
            if (kg > rq0     || mk0 == 0) s[jf][0] = -1.0e9f;
            if (kg + 1 > rq0 || mk1 == 0) s[jf][1] = -1.0e9f;
            if (kg > rq1     || mk0 == 0) s[jf][2] = -1.0e9f;
            if (kg + 1 > rq1 || mk1 == 0) s[jf][3] = -1.0e9f;
        }

        // ---- online softmax ----
        float mt0 = -3.0e38f, mt1 = -3.0e38f;
        #pragma unroll
        for (int jf = 0; jf < 8; jf++) {
            mt0 = fmaxf(mt0, fmaxf(s[jf][0], s[jf][1]));
            mt1 = fmaxf(mt1, fmaxf(s[jf][2], s[jf][3]));
        }
        mt0 = fmaxf(mt0, __shfl_xor_sync(0xffffffffu, mt0, 1));
        mt0 = fmaxf(mt0, __shfl_xor_sync(0xffffffffu, mt0, 2));
        mt1 = fmaxf(mt1, __shfl_xor_sync(0xffffffffu, mt1, 1));
        mt1 = fmaxf(mt1, __shfl_xor_sync(0xffffffffu, mt1, 2));
        float mn0 = fmaxf(m0, mt0), mn1 = fmaxf(m1, mt1);
        float sc0 = __expf(m0 - mn0), sc1 = __expf(m1 - mn1);
        float ls0 = 0.f, ls1 = 0.f;
        #pragma unroll
        for (int jf = 0; jf < 8; jf++) {
            s[jf][0] = __expf(s[jf][0] - mn0);
            s[jf][1] = __expf(s[jf][1] - mn0);
            s[jf][2] = __expf(s[jf][2] - mn1);
            s[jf][3] = __expf(s[jf][3] - mn1);
            ls0 += s[jf][0] + s[jf][1];
            ls1 += s[jf][2] + s[jf][3];
        }
        ls0 += __shfl_xor_sync(0xffffffffu, ls0, 1);
        ls0 += __shfl_xor_sync(0xffffffffu, ls0, 2);
        ls1 += __shfl_xor_sync(0xffffffffu, ls1, 1);
        ls1 += __shfl_xor_sync(0xffffffffu, ls1, 2);
        l0 = l0 * sc0 + ls0;
        l1 = l1 * sc1 + ls1;
        m0 = mn0; m1 = mn1;
        #pragma unroll
        for (int jf = 0; jf < 8; jf++) {
            o[jf][0] *= sc0; o[jf][1] *= sc0;
            o[jf][2] *= sc1; o[jf][3] *= sc1;
        }

        // ---- P @ V (P single fp16; 1-pass) ----
        #pragma unroll
        for (int ks = 0; ks < 4; ks++) {
            uint32_t ph[4];
            ph[0] = pack2_f16(s[2*ks][0],   s[2*ks][1]);
            ph[1] = pack2_f16(s[2*ks][2],   s[2*ks][3]);
            ph[2] = pack2_f16(s[2*ks+1][0], s[2*ks+1][1]);
            ph[3] = pack2_f16(s[2*ks+1][2], s[2*ks+1][3]);
            #pragma unroll
            for (int nj = 0; nj < 4; nj++) {
                uint32_t vv[4];
                uint32_t off = bOff + (uint32_t)nj * 16 * AROWB + (uint32_t)ks * 32;
                ldsm_x4(vv, vbase + off);
                mma_f16(o[2*nj],   ph, vv[0], vv[1]);
                mma_f16(o[2*nj+1], ph, vv[2], vv[3]);
            }
        }

        // ---- store prefetched tile into alternate stage ----
        if (j < jmax) {
            store_kv(cur ^ 1, pk, pv, pm);
            __syncthreads();
        }
    }

    // ---- epilogue: write ctx as single fp16 plane ----
    float inv0 = 1.0f / l0, inv1 = 1.0f / l1;
    bool dg0 = (m0 < -1.0e8f), dg1 = (m1 < -1.0e8f);
    #pragma unroll
    for (int jf = 0; jf < 8; jf++) {
        int col = h * DK_ + jf * 8 + colb;
        const float* vm = vmean + b * D_ + col;
        float2 w0, w1;
        w0.x = dg0 ? vm[0] : o[jf][0] * inv0;
        w0.y = dg0 ? vm[1] : o[jf][1] * inv0;
        w1.x = dg1 ? vm[0] : o[jf][2] * inv1;
        w1.y = dg1 ? vm[1] : o[jf][3] * inv1;
        *(uint32_t*)(ctx + (size_t)(b * S_ + rq0) * D_ + col) = pack2_f16(w0.x, w0.y);
        *(uint32_t*)(ctx + (size_t)(b * S_ + rq1) * D_ + col) = pack2_f16(w1.x, w1.y);
    }
}

// ---------------- launch ---------------------------------------------------
extern "C" void kernel_launch(void* const* d_in, const int* in_sizes, int n_in,
                              void* d_out, int out_size)
{
    (void)in_sizes; (void)n_in; (void)out_size;
    const float* x     = (const float*)d_in[0];
    const int*   amask = (const int*)  d_in[1];
    const float* Wq = (const float*)d_in[2];  const float* bq = (const float*)d_in[3];
    const float* Wk = (const float*)d_in[4];  const float* bk = (const float*)d_in[5];
    const float* Wv = (const float*)d_in[6];  const float* bv = (const float*)d_in[7];
    const float* Wo = (const float*)d_in[8];  const float* bo = (const float*)d_in[9];
    const float* W1 = (const float*)d_in[10]; const float* b1 = (const float*)d_in[11];
    const float* W2 = (const float*)d_in[12]; const float* b2 = (const float*)d_in[13];
    const float* g1 = (const float*)d_in[14]; const float* be1 = (const float*)d_in[15];
    const float* g2 = (const float*)d_in[16]; const float* be2 = (const float*)d_in[17];
    float* out = (float*)d_out;

    float *vmean, *bqkv;
    __half *hb, *qkv, *ctx, *a;
    __half *wqkvt, *wot, *w1t, *w2t;
    cudaGetSymbolAddress((void**)&vmean, g_vmean);
    cudaGetSymbolAddress((void**)&bqkv,  g_bqkv);
    cudaGetSymbolAddress((void**)&hb,    g_h);
    cudaGetSymbolAddress((void**)&qkv,   g_qkv);
    cudaGetSymbolAddress((void**)&ctx,   g_ctx);
    cudaGetSymbolAddress((void**)&a,     g_a);
    cudaGetSymbolAddress((void**)&wqkvt, g_wqkvt);
    cudaGetSymbolAddress((void**)&wot,   g_wot);
    cudaGetSymbolAddress((void**)&w1t,   g_w1t);
    cudaGetSymbolAddress((void**)&w2t,   g_w2t);

    cudaFuncSetAttribute(attn2_kernel, cudaFuncAttributeMaxDynamicSharedMemorySize, ATT2_SMEM);
    cudaFuncSetAttribute(mgemm_kernel<EPI_BIAS, 1>,      cudaFuncAttributeMaxDynamicSharedMemorySize, MGEMM_SMEM);
    cudaFuncSetAttribute(mgemm_kernel<EPI_BIAS_RES, 0>,  cudaFuncAttributeMaxDynamicSharedMemorySize, MGEMM_SMEM);
    cudaFuncSetAttribute(mgemm_kernel<EPI_BIAS_GELU, 1>, cudaFuncAttributeMaxDynamicSharedMemorySize, MGEMM_SMEM);

    dim3 tb(32, 8);
    transpose_cvt4_kernel<<<dim3(D_ / 32, D_ / 32, 4), tb>>>(
        Wq, Wk, Wv, Wo,
        wqkvt, wqkvt + (size_t)D_ * D_, wqkvt + (size_t)2 * D_ * D_, wot,
        bq, bk, bv, bqkv, vmean);
    transpose_cvt_kernel<<<dim3(F_ / 32, D_ / 32), tb>>>(W1, w1t, D_, F_);
    transpose_cvt_kernel<<<dim3(D_ / 32, F_ / 32), tb>>>(W2, w2t, F_, D_);

    dim3 gD(D_ / 128, NTOK / 128);     // (8, 64)
    dim3 gQKV(LD3 / 128, NTOK / 128);  // (24, 64)
    dim3 gF(F_ / 128, NTOK / 128);     // (32, 64)

    // attention sublayer (pre-norm)
    ln_kernel<<<NTOK / 8, 256>>>(x, g1, be1, hb);
    mgemm_kernel<EPI_BIAS, 1><<<gQKV, 256, MGEMM_SMEM>>>(hb, wqkvt, bqkv, nullptr, nullptr, qkv, NTOK, LD3, D_);
    vmean_acc<<<dim3(4, 8), 1024>>>(qkv, vmean);
    attn2_kernel<<<dim3(S_ / 128, B_ * H_), 256, ATT2_SMEM>>>(qkv, amask, vmean, ctx);
    mgemm_kernel<EPI_BIAS_RES, 0><<<gD, 256, MGEMM_SMEM>>>(ctx, wot, bo, x, out, nullptr, NTOK, D_, D_);

    // FFN sublayer (pre-norm)
    ln_kernel<<<NTOK / 8, 256>>>(out, g2, be2, hb);
    mgemm_kernel<EPI_BIAS_GELU, 1><<<gF, 256, MGEMM_SMEM>>>(hb, w1t, b1, nullptr, nullptr, a, NTOK, F_, D_);
    mgemm_kernel<EPI_BIAS_RES, 0><<<gD, 256, MGEMM_SMEM>>>(a, w2t, b2, out, out, nullptr, NTOK, D_, F_);
}